// round 9
// baseline (speedup 1.0000x reference)
#include <cuda_runtime.h>
#include <cstdint>

#define VOCAB 100000
#define BATCH 2048
#define SEQ   50
#define HID   256
#define KIN   512

// ---------------- scratch (device globals; no allocation allowed) ----------
__device__ float g_bow_h[BATCH * HID];
__device__ float g_beo_h[BATCH * HID];
// epilogue K-split partials: [side*2+khalf][row][72] (64 embd + 5 pred + pad)
__device__ float g_part[2 * 2 * BATCH * 72];

__device__ __forceinline__ float lky(float v) {
    return (v > 0.f) ? v : 0.2f * v;
}

// ============================================================================
// Fused kernel. Grid 2176: idx % 17 == 0 -> beo GEMM block (128 of them),
// else bow gather block (2048, one batch row each). 256 threads.
// Dynamic smem = max(GemmSm, GatherSm) ~= 51 KB -> 4 blocks/SM.
// ============================================================================
#define BM 64
#define BN 64
#define BK 32
#define NBLK 2176

struct GemmSm {
    float As[BM][BK + 4];
    float Bs[BK][BN];
};
struct GatherSm {
    float buf[SEQ][HID];          // 50 KB staged token rows
    int   toks[SEQ];
    float keep[SEQ];
    unsigned int wbuf[SEQ];
    int   is64;
};
#define SMEM_DYN (sizeof(GatherSm) > sizeof(GemmSm) ? sizeof(GatherSm) : sizeof(GemmSm))

__device__ __forceinline__ void cp_async16(uint32_t dst_smem, const void* src) {
    asm volatile("cp.async.cg.shared.global [%0], [%1], 16;"
                 :: "r"(dst_smem), "l"(src));
}

__global__ __launch_bounds__(256, 4) void fused_hidden_kernel(
    const unsigned int* __restrict__ s_words,
    const float* __restrict__ Wh,    const float* __restrict__ bh,
    const float* __restrict__ X,     const float* __restrict__ W,
    const float* __restrict__ bias)
{
    extern __shared__ __align__(16) char dynsm[];
    const int tid = threadIdx.x;
    const int idx = blockIdx.x;

    if (idx % 17 == 0) {
        // ------------------------- beo GEMM path ---------------------------
        GemmSm& sg = *reinterpret_cast<GemmSm*>(dynsm);
        const int bx = idx / 17;                 // 0..127
        const int m0 = (bx >> 2) * BM;
        const int n0 = (bx & 3) * BN;
        const int tx = tid & 15;
        const int ty = tid >> 4;

        unsigned long long acc[4][2];
        #pragma unroll
        for (int r = 0; r < 4; r++) { acc[r][0] = 0ull; acc[r][1] = 0ull; }

        for (int k0 = 0; k0 < KIN; k0 += BK) {
            #pragma unroll
            for (int f = tid; f < BM * BK / 4; f += 256) {
                int r = f >> 3, q = f & 7;
                *(float4*)&sg.As[r][q * 4] =
                    *(const float4*)&X[(m0 + r) * KIN + k0 + q * 4];
            }
            #pragma unroll
            for (int f = tid; f < BK * BN / 4; f += 256) {
                int kr = f >> 4, nq = f & 15;
                *(float4*)&sg.Bs[kr][nq * 4] =
                    *(const float4*)&W[(k0 + kr) * HID + n0 + nq * 4];
            }
            __syncthreads();

            #pragma unroll
            for (int k = 0; k < BK; k++) {
                float4 bv = *(const float4*)&sg.Bs[k][tx * 4];
                unsigned long long pb0, pb1;
                asm("mov.b64 %0, {%1, %2};" : "=l"(pb0) : "f"(bv.x), "f"(bv.y));
                asm("mov.b64 %0, {%1, %2};" : "=l"(pb1) : "f"(bv.z), "f"(bv.w));
                #pragma unroll
                for (int r = 0; r < 4; r++) {
                    float av = sg.As[ty * 4 + r][k];
                    unsigned long long pa;
                    asm("mov.b64 %0, {%1, %1};" : "=l"(pa) : "f"(av));
                    asm("fma.rn.f32x2 %0, %1, %2, %0;" : "+l"(acc[r][0]) : "l"(pa), "l"(pb0));
                    asm("fma.rn.f32x2 %0, %1, %2, %0;" : "+l"(acc[r][1]) : "l"(pa), "l"(pb1));
                }
            }
            __syncthreads();
        }

        const float4 bb = *(const float4*)&bias[n0 + tx * 4];
        #pragma unroll
        for (int r = 0; r < 4; r++) {
            float o0, o1, o2, o3;
            asm("mov.b64 {%0, %1}, %2;" : "=f"(o0), "=f"(o1) : "l"(acc[r][0]));
            asm("mov.b64 {%0, %1}, %2;" : "=f"(o2), "=f"(o3) : "l"(acc[r][1]));
            *(float4*)&g_beo_h[(m0 + ty * 4 + r) * HID + n0 + tx * 4] =
                make_float4(lky(o0 + bb.x), lky(o1 + bb.y),
                            lky(o2 + bb.z), lky(o3 + bb.w));
        }
    } else {
        // ------------------------- bow gather path -------------------------
        GatherSm& sb = *reinterpret_cast<GatherSm*>(dynsm);
        const int row   = idx - idx / 17 - 1;    // 0..2047
        const int wbase = row * SEQ;

        // Phase 1: read 50 words at int32 positions (in-bounds both dtypes)
        if (tid < SEQ) sb.wbuf[tid] = s_words[wbase + tid];
        __syncthreads();

        // Phase 2: dtype detect. Under int64, words at ODD GLOBAL index are
        // zero high-halves. Local i maps to global wbase+i.
        if (tid == 0) {
            int all0 = 1;
            const int off = 1 - (wbase & 1);     // local parity of odd globals
            for (int i = off; i < SEQ; i += 2) all0 &= (sb.wbuf[i] == 0u);
            sb.is64 = all0;
        }
        __syncthreads();

        // Phase 3: tokens under detected layout
        const int is64 = sb.is64;
        if (tid < SEQ) {
            sb.toks[tid] = is64 ? (int)s_words[2 * (wbase + tid)]
                                : (int)sb.wbuf[tid];
        }
        __syncthreads();

        // Phase 4: first-occurrence keep mask (set semantics)
        if (tid < SEQ) {
            int t = sb.toks[tid];
            float k = 1.0f;
            for (int j2 = 0; j2 < tid; j2++)
                if (sb.toks[j2] == t) { k = 0.0f; break; }
            sb.keep[tid] = k;
        }
        __syncthreads();

        // Phase 5: stage all 50 token rows via cp.async (register-free MLP).
        // 50 rows x 64 chunks(16B) = 3200 ops; 12-13 per thread.
        {
            const uint32_t buf_base =
                (uint32_t)__cvta_generic_to_shared(&sb.buf[0][0]);
            for (int c = tid; c < SEQ * 64; c += 256) {
                const int i = c >> 6;            // token index
                const int q = c & 63;            // 16B chunk within row
                const char* src = (const char*)(Wh + (size_t)sb.toks[i] * HID)
                                  + q * 16;
                cp_async16(buf_base + (uint32_t)(i * HID * 4 + q * 16), src);
            }
            asm volatile("cp.async.commit_group;" ::: "memory");
            asm volatile("cp.async.wait_group 0;" ::: "memory");
        }
        __syncthreads();

        // Phase 6: reduce 50 rows; 1 col/thread, 4 independent chains
        {
            const int c = tid;
            float a0 = 0.f, a1 = 0.f, a2 = 0.f, a3 = 0.f;
            #pragma unroll
            for (int i = 0; i < 48; i += 4) {
                a0 = fmaf(sb.keep[i + 0], sb.buf[i + 0][c], a0);
                a1 = fmaf(sb.keep[i + 1], sb.buf[i + 1][c], a1);
                a2 = fmaf(sb.keep[i + 2], sb.buf[i + 2][c], a2);
                a3 = fmaf(sb.keep[i + 3], sb.buf[i + 3][c], a3);
            }
            a0 = fmaf(sb.keep[48], sb.buf[48][c], a0);
            a1 = fmaf(sb.keep[49], sb.buf[49][c], a1);
            float v = ((a0 + a1) + (a2 + a3)) + bh[c];
            g_bow_h[row * HID + c] = lky(v);
        }
    }
}

// ============================================================================
// K3 v5: epilogue with K-split. grid (128, 2 sides, 2 khalf) = 512 blocks.
// ============================================================================
#define EPB 16
#define HP  20

union EpSmem {
    float WeS[128][64];
    struct {
        float red[4][EPB][64];
        float predred[EPB * 10];
    } r;
};

__global__ __launch_bounds__(256) void epilogue_kernel(
    const float* __restrict__ We_bow, const float* __restrict__ Wp_bow,
    const float* __restrict__ We_beo, const float* __restrict__ Wp_beo)
{
    __shared__ __align__(16) float sh_t[128][HP];
    __shared__ EpSmem u;

    const int side = blockIdx.y;
    const int kh   = blockIdx.z;
    const int row0 = blockIdx.x * EPB;
    const int tid  = threadIdx.x;
    const int kg0  = kh * 128;

    const float* H  = side ? g_beo_h : g_bow_h;
    const float* We = side ? We_beo : We_bow;
    const float* Wp = side ? Wp_beo : Wp_bow;

    #pragma unroll
    for (int f = tid; f < EPB * 32; f += 256) {
        int r = f & 15, cq = f >> 4;
        float4 v = *(const float4*)&H[(row0 + r) * HID + kg0 + cq * 4];
        sh_t[cq * 4 + 0][r] = v.x;
        sh_t[cq * 4 + 1][r] = v.y;
        sh_t[cq * 4 + 2][r] = v.z;
        sh_t[cq * 4 + 3][r] = v.w;
    }
    #pragma unroll
    for (int f = tid; f < 128 * 16; f += 256) {
        int kr = f >> 4, nq = f & 15;
        *(float4*)&u.WeS[kr][nq * 4] =
            *(const float4*)&We[(kg0 + kr) * 64 + nq * 4];
    }
    __syncthreads();

    const int cg = tid & 15;
    const int rg = (tid >> 4) & 3;
    const int kp = tid >> 6;

    unsigned long long acc[4][2];
    #pragma unroll
    for (int r = 0; r < 4; r++) { acc[r][0] = 0ull; acc[r][1] = 0ull; }

    #pragma unroll 8
    for (int k = 0; k < 32; k++) {
        const int kk = kp * 32 + k;
        float4 hv = *(const float4*)&sh_t[kk][rg * 4];
        float4 wv = *(const float4*)&u.WeS[kk][cg * 4];
        unsigned long long pw0, pw1;
        asm("mov.b64 %0, {%1, %2};" : "=l"(pw0) : "f"(wv.x), "f"(wv.y));
        asm("mov.b64 %0, {%1, %2};" : "=l"(pw1) : "f"(wv.z), "f"(wv.w));
        unsigned long long ph0, ph1, ph2, ph3;
        asm("mov.b64 %0, {%1, %1};" : "=l"(ph0) : "f"(hv.x));
        asm("mov.b64 %0, {%1, %1};" : "=l"(ph1) : "f"(hv.y));
        asm("mov.b64 %0, {%1, %1};" : "=l"(ph2) : "f"(hv.z));
        asm("mov.b64 %0, {%1, %1};" : "=l"(ph3) : "f"(hv.w));
        asm("fma.rn.f32x2 %0, %1, %2, %0;" : "+l"(acc[0][0]) : "l"(ph0), "l"(pw0));
        asm("fma.rn.f32x2 %0, %1, %2, %0;" : "+l"(acc[0][1]) : "l"(ph0), "l"(pw1));
        asm("fma.rn.f32x2 %0, %1, %2, %0;" : "+l"(acc[1][0]) : "l"(ph1), "l"(pw0));
        asm("fma.rn.f32x2 %0, %1, %2, %0;" : "+l"(acc[1][1]) : "l"(ph1), "l"(pw1));
        asm("fma.rn.f32x2 %0, %1, %2, %0;" : "+l"(acc[2][0]) : "l"(ph2), "l"(pw0));
        asm("fma.rn.f32x2 %0, %1, %2, %0;" : "+l"(acc[2][1]) : "l"(ph2), "l"(pw1));
        asm("fma.rn.f32x2 %0, %1, %2, %0;" : "+l"(acc[3][0]) : "l"(ph3), "l"(pw0));
        asm("fma.rn.f32x2 %0, %1, %2, %0;" : "+l"(acc[3][1]) : "l"(ph3), "l"(pw1));
    }
    __syncthreads();

    #pragma unroll
    for (int r = 0; r < 4; r++) {
        float a0, a1, a2, a3;
        asm("mov.b64 {%0, %1}, %2;" : "=f"(a0), "=f"(a1) : "l"(acc[r][0]));
        asm("mov.b64 {%0, %1}, %2;" : "=f"(a2), "=f"(a3) : "l"(acc[r][1]));
        *(float4*)&u.r.red[kp][rg * 4 + r][cg * 4] = make_float4(a0, a1, a2, a3);
    }

    if (tid < EPB * 10) {
        int r   = tid / 10;
        int rem = tid - r * 10;
        int j   = rem % 5;
        int kq  = rem / 5;
        const int kb = kq * 64;
        float a0 = 0.f, a1 = 0.f, a2 = 0.f, a3 = 0.f;
        #pragma unroll 4
        for (int k = 0; k < 64; k += 4) {
            a0 = fmaf(sh_t[kb + k + 0][r], Wp[(kg0 + kb + k + 0) * 5 + j], a0);
            a1 = fmaf(sh_t[kb + k + 1][r], Wp[(kg0 + kb + k + 1) * 5 + j], a1);
            a2 = fmaf(sh_t[kb + k + 2][r], Wp[(kg0 + kb + k + 2) * 5 + j], a2);
            a3 = fmaf(sh_t[kb + k + 3][r], Wp[(kg0 + kb + k + 3) * 5 + j], a3);
        }
        u.r.predred[tid] = (a0 + a1) + (a2 + a3);
    }
    __syncthreads();

    float* P = &g_part[((size_t)(side * 2 + kh) * BATCH) * 72];
    {
        const int rr = tid >> 4;
        const int c4 = (tid & 15) * 4;
        float4 p0 = *(const float4*)&u.r.red[0][rr][c4];
        float4 p1 = *(const float4*)&u.r.red[1][rr][c4];
        float4 p2 = *(const float4*)&u.r.red[2][rr][c4];
        float4 p3 = *(const float4*)&u.r.red[3][rr][c4];
        *(float4*)&P[(row0 + rr) * 72 + c4] =
            make_float4((p0.x + p1.x) + (p2.x + p3.x),
                        (p0.y + p1.y) + (p2.y + p3.y),
                        (p0.z + p1.z) + (p2.z + p3.z),
                        (p0.w + p1.w) + (p2.w + p3.w));
    }
    if (tid < EPB * 5) {
        int r = tid / 5, j = tid - r * 5;
        P[(row0 + r) * 72 + 64 + j] =
            u.r.predred[r * 10 + j] + u.r.predred[r * 10 + 5 + j];
    }
}

// ============================================================================
// Combine kernel: out = part[kh=0] + part[kh=1] + bias. grid (552, 2).
// ============================================================================
__global__ __launch_bounds__(256) void combine_kernel(
    const float* __restrict__ be_bow, const float* __restrict__ bp_bow,
    const float* __restrict__ be_beo, const float* __restrict__ bp_beo,
    float* __restrict__ out)
{
    const int side = blockIdx.y;
    const int e    = blockIdx.x * 256 + threadIdx.x;
    if (e >= BATCH * 69) return;

    const float* P0 = &g_part[((size_t)(side * 2 + 0) * BATCH) * 72];
    const float* P1 = &g_part[((size_t)(side * 2 + 1) * BATCH) * 72];

    if (e < BATCH * 64) {
        int row = e >> 6, c = e & 63;
        float b = side ? be_beo[c] : be_bow[c];
        out[(side ? BATCH * 64 : 0) + e] =
            P0[row * 72 + c] + P1[row * 72 + c] + b;
    } else {
        int e2 = e - BATCH * 64;
        int row = e2 / 5, j = e2 - row * 5;
        float b = side ? bp_beo[j] : bp_bow[j];
        out[BATCH * 128 + side * BATCH * 5 + e2] =
            P0[row * 72 + 64 + j] + P1[row * 72 + 64 + j] + b;
    }
}

// ============================================================================
extern "C" void kernel_launch(void* const* d_in, const int* in_sizes, int n_in,
                              void* d_out, int out_size)
{
    const unsigned int* s_words = (const unsigned int*)d_in[0];
    const float* x        = (const float*)d_in[1];
    const float* W_bow_h  = (const float*)d_in[2];
    const float* b_bow_h  = (const float*)d_in[3];
    const float* W_bow_p  = (const float*)d_in[4];
    const float* b_bow_p  = (const float*)d_in[5];
    const float* W_bow_e  = (const float*)d_in[6];
    const float* b_bow_e  = (const float*)d_in[7];
    const float* W_beo_h  = (const float*)d_in[8];
    const float* b_beo_h  = (const float*)d_in[9];
    const float* W_beo_p  = (const float*)d_in[10];
    const float* b_beo_p  = (const float*)d_in[11];
    const float* W_beo_e  = (const float*)d_in[12];
    const float* b_beo_e  = (const float*)d_in[13];
    float* out = (float*)d_out;

    static int attr_set = 0;
    if (!attr_set) {
        cudaFuncSetAttribute(fused_hidden_kernel,
                             cudaFuncAttributeMaxDynamicSharedMemorySize,
                             (int)SMEM_DYN);
        attr_set = 1;
    }

    fused_hidden_kernel<<<NBLK, 256, SMEM_DYN>>>(
        s_words, W_bow_h, b_bow_h, x, W_beo_h, b_beo_h);

    dim3 g3(BATCH / EPB, 2, 2);
    epilogue_kernel<<<g3, 256>>>(W_bow_e, W_bow_p, W_beo_e, W_beo_p);

    dim3 g4((BATCH * 69 + 255) / 256, 2);
    combine_kernel<<<g4, 256>>>(b_bow_e, b_bow_p, b_beo_e, b_beo_p, out);
}